// round 15
// baseline (speedup 1.0000x reference)
#include <cuda_runtime.h>
#include <cuda_bf16.h>
#include <math.h>
#include <stdint.h>

#define B_    128
#define H_    512
#define F_    16
#define HID_  64
#define NF_   257
#define M_    (B_*F_)       // 2048
#define K_    (NF_*HID_)    // 16448
#define NPAD_ 288
#define SPLITS_ 9

// ---------------- scratch (static device memory; no allocations) ----------------
__device__ __align__(128) float g_fft_re[M_*NF_];
__device__ __align__(128) float g_fft_im[M_*NF_];
__device__ __align__(128) float g_new_re[M_*NF_];
__device__ __align__(128) float g_new_im[M_*NF_];
__device__ __align__(128) __nv_bfloat16 g_wt[(size_t)NPAD_*K_];   // W_gate^T [n][k] bf16
__device__ __align__(128) float g_part[SPLITS_][(size_t)M_*NPAD_];
__device__ __align__(128) __nv_bfloat16 g_flat[(size_t)M_*K_];    // proj bf16, [m][n*64+h]

// ================= helpers =================
#define CP_ASYNC16(dst, src) \
    asm volatile("cp.async.cg.shared.global [%0], [%1], 16;\n" :: "r"(dst), "l"(src))
__device__ __forceinline__ uint32_t smem_u32(const void* p) {
    uint32_t a;
    asm("{ .reg .u64 t; cvta.to.shared.u64 t, %1; cvt.u32.u64 %0, t; }" : "=r"(a) : "l"(p));
    return a;
}
__device__ __forceinline__ void mma_bf16(float c[4], const uint32_t a[4], const uint32_t b[2]) {
    asm volatile(
        "mma.sync.aligned.m16n8k16.row.col.f32.bf16.bf16.f32 "
        "{%0,%1,%2,%3}, {%4,%5,%6,%7}, {%8,%9}, {%0,%1,%2,%3};"
        : "+f"(c[0]), "+f"(c[1]), "+f"(c[2]), "+f"(c[3])
        : "r"(a[0]), "r"(a[1]), "r"(a[2]), "r"(a[3]), "r"(b[0]), "r"(b[1]));
}
#define LDSM_X4(R0, R1, R2, R3, ADDR) \
    asm volatile("ldmatrix.sync.aligned.m8n8.x4.shared.b16 {%0,%1,%2,%3}, [%4];" \
        : "=r"(R0), "=r"(R1), "=r"(R2), "=r"(R3) : "r"(ADDR))
__device__ __forceinline__ uint32_t packbf(float x, float y) {
    __nv_bfloat162 h = __float22bfloat162_rn(make_float2(x, y));
    return *(uint32_t*)&h;
}
__device__ __forceinline__ float sigf(float x) {
    return __fdividef(1.f, 1.f + __expf(-x));
}
#define SC_ORTHO 0.044194173824159216f

// ---------------- batched N-channel 512-pt Stockham FFT (512 threads) ----------------
__device__ __forceinline__ void fft512x8(float* r0, float* i0, float* r1, float* i1,
                                         const float* tc, const float* ts,
                                         int tid, float*& outr, float*& outi)
{
    float *ar = r0, *ai = i0, *br = r1, *bi = i1;
    int u = tid & 255, cb = (tid >> 8) << 2;
#pragma unroll
    for (int st = 0; st < 9; st++) {
        __syncthreads();
        int m = 1 << st;
        int j = u >> st, k = u & (m - 1), idx = u & ~(m - 1);
        float wc = tc[idx], ws = ts[idx];
        int o0 = k + (j << (st + 1));
#pragma unroll
        for (int q = 0; q < 4; q++) {
            int off = (cb + q) << 9;
            float c0r = ar[off + u],       c0i = ai[off + u];
            float c1r = ar[off + u + 256], c1i = ai[off + u + 256];
            float sr = c0r - c1r, si = c0i - c1i;
            br[off + o0]     = c0r + c1r;
            bi[off + o0]     = c0i + c1i;
            br[off + o0 + m] = wc * sr - ws * si;
            bi[off + o0 + m] = wc * si + ws * sr;
        }
        float* t;
        t = ar; ar = br; br = t;
        t = ai; ai = bi; bi = t;
    }
    __syncthreads();
    outr = ar; outi = ai;
}

// 5-channel: channels {tid>>8, 2+(tid>>8)} for all threads, channel 4 for tid<256
__device__ __forceinline__ void fft512x5(float* r0, float* i0, float* r1, float* i1,
                                         const float* tc, const float* ts,
                                         int tid, float*& outr, float*& outi)
{
    float *ar = r0, *ai = i0, *br = r1, *bi = i1;
    int u = tid & 255;
    int c0ch = tid >> 8;            // 0 or 1
#pragma unroll
    for (int st = 0; st < 9; st++) {
        __syncthreads();
        int m = 1 << st;
        int j = u >> st, k = u & (m - 1), idx = u & ~(m - 1);
        float wc = tc[idx], ws = ts[idx];
        int o0 = k + (j << (st + 1));
#pragma unroll
        for (int q = 0; q < 2; q++) {
            int off = (c0ch + q * 2) << 9;
            float c0r = ar[off + u],       c0i = ai[off + u];
            float c1r = ar[off + u + 256], c1i = ai[off + u + 256];
            float sr = c0r - c1r, si = c0i - c1i;
            br[off + o0]     = c0r + c1r;
            bi[off + o0]     = c0i + c1i;
            br[off + o0 + m] = wc * sr - ws * si;
            bi[off + o0 + m] = wc * si + ws * sr;
        }
        if (tid < 256) {
            int off = 4 << 9;
            float c0r = ar[off + u],       c0i = ai[off + u];
            float c1r = ar[off + u + 256], c1i = ai[off + u + 256];
            float sr = c0r - c1r, si = c0i - c1i;
            br[off + o0]     = c0r + c1r;
            bi[off + o0]     = c0i + c1i;
            br[off + o0 + m] = wc * sr - ws * si;
            bi[off + o0 + m] = wc * si + ws * sr;
        }
        float* t;
        t = ar; ar = br; br = t;
        t = ai; ai = bi; bi = t;
    }
    __syncthreads();
    outr = ar; outi = ai;
}

// ---------------- kernel 1: fwd — packed real FFTs, inline unpack, ch-outer proj loop ----------------
// smem floats: r0 @0 (2560), i0 @2560, r1 @5120, i1 @7680, s @10240 (512),
// sp @10752 (1024), tc @11776 (256), ts @12032 (256), wp @12288 (256), bp @12544 (64)
#define FWD_SMEMF 12608
#define NHEAVY_   (B_*2)    // 256 (batch, channel-half) blocks
#define NT_BLKS_  (257*9)   // 2313 transpose tiles (64k x 32n)

__global__ void __launch_bounds__(512, 3) k_fwd(
    const float* __restrict__ x,
    const float* __restrict__ Wp,  const float* __restrict__ bp,
    const float* __restrict__ mag_w, const float* __restrict__ mag_b,
    const float* __restrict__ ph_w,  const float* __restrict__ ph_b,
    const float* __restrict__ Wg)
{
    extern __shared__ __align__(16) float sm[];
    int tid = threadIdx.x;

    if (blockIdx.x >= NHEAVY_) {
        // ---- transpose tile: Wg[K][257] -> g_wt[288][K] bf16 (zero pad) ----
        float* tile = sm;                       // [64][33]
        int t  = blockIdx.x - NHEAVY_;
        int kt = t % 257, nt = t / 257;
        int kb = kt * 64, nb = nt * 32;
        int col = tid & 31, rowb = tid >> 5;
#pragma unroll
        for (int rr = 0; rr < 4; rr++) {
            int row = rowb + rr * 16;
            int nn = nb + col;
            tile[row * 33 + col] = (nn < NF_) ? Wg[(size_t)(kb + row) * NF_ + nn] : 0.f;
        }
        __syncthreads();
#pragma unroll
        for (int i = 0; i < 4; i++) {
            int e = tid + i * 512;
            int nl = e >> 6, kl = e & 63;
            g_wt[(size_t)(nb + nl) * K_ + kb + kl] = __float2bfloat16(tile[kl * 33 + nl]);
        }
        return;
    }

    // ---- heavy block: batch b, channel-half g ----
    int b = blockIdx.x >> 1;
    int g = blockIdx.x & 1;
    float* r0  = sm;
    float* i0  = sm + 2560;
    float* r1  = sm + 5120;
    float* i1  = sm + 7680;
    float* s   = sm + 10240;
    float* sp  = sm + 10752;   // zero-padded: sp[i] = s[i-255] for i in [255,767)
    float* tc  = sm + 11776;
    float* ts  = sm + 12032;
    float* wp  = sm + 12288;
    float* bpp = sm + 12544;

    if (tid < 256) {
        float _s, _c;
        sincosf(-3.14159265358979323846f * (float)tid * (1.0f / 256.0f), &_s, &_c);
        tc[tid] = _c; ts[tid] = _s;
    } else {
        wp[tid - 256] = Wp[tid - 256];
    }
    if (tid < 64) bpp[tid] = bp[tid];

    // channel sum -> s, zero sp wings; also load 8 packed channels (4 complex)
    {
        const float4* xr = (const float4*)(x + (size_t)b * 512 * 16);
        float4 a = xr[tid * 4 + 0], c = xr[tid * 4 + 1], d = xr[tid * 4 + 2], e = xr[tid * 4 + 3];
        s[tid] = (a.x + a.y + a.z + a.w) + (c.x + c.y + c.z + c.w)
               + (d.x + d.y + d.z + d.w) + (e.x + e.y + e.z + e.w);
        sp[tid] = 0.f;
        sp[512 + tid] = 0.f;
#pragma unroll
        for (int i = 0; i < 2; i++) {
            int e2 = tid + i * 512;           // 0..1023
            int t = e2 >> 1, j = e2 & 1;
            float4 v = xr[t * 4 + g * 2 + j];
            int p0 = j * 2;
            r0[(p0 + 0) * 512 + t] = v.x; i0[(p0 + 0) * 512 + t] = v.y;
            r0[(p0 + 1) * 512 + t] = v.z; i0[(p0 + 1) * 512 + t] = v.w;
        }
    }
    __syncthreads();
    sp[255 + tid] = s[tid];
    __syncthreads();

    // autocorrelation -> slot 4 (csd channel)
    {
        int t = tid;
        float acc0 = 0.f, acc1 = 0.f, acc2 = 0.f, acc3 = 0.f;
#pragma unroll 4
        for (int k = 0; k < 512; k += 4) {
            float4 sk = *(const float4*)&s[k];
            acc0 = fmaf(sp[t + k + 0], sk.x, acc0);
            acc1 = fmaf(sp[t + k + 1], sk.y, acc1);
            acc2 = fmaf(sp[t + k + 2], sk.z, acc2);
            acc3 = fmaf(sp[t + k + 3], sk.w, acc3);
        }
        r0[2048 + t] = (acc0 + acc1) + (acc2 + acc3);
        i0[2048 + t] = 0.f;
    }

    float *gfr, *gfi;
    fft512x5(r0, i0, r1, i1, tc, ts, tid, gfr, gfi);

    // features + proj + heads: 16-lane team per (ch, n); ch outer (no division)
    {
        const float SCC = SC_ORTHO / 256.0f;
        int lane16 = tid & 15;         // h-chunk owner: h in [lane16*4, lane16*4+4)
        int team   = tid >> 4;         // 32 teams
        int h0 = lane16 * 4;
        float4 w0 = *(const float4*)&wp[h0];
        float4 w1 = *(const float4*)&wp[64 + h0];
        float4 w2 = *(const float4*)&wp[128 + h0];
        float4 w3 = *(const float4*)&wp[192 + h0];
        float4 bb = *(const float4*)&bpp[h0];

#pragma unroll 2
        for (int ch = 0; ch < 8; ch++) {
            int p = ch >> 1, odd = ch & 1;
            const float* gr = gfr + p * 512;
            const float* gi = gfi + p * 512;
            int m = b * 16 + g * 8 + ch;
            __nv_bfloat16* frow = g_flat + (size_t)m * K_ + h0;
            size_t mrow = (size_t)m * NF_;

            for (int n = team; n < NF_; n += 32) {
                int ml = (512 - n) & 511;
                float zr = gr[n],  zi = gi[n];
                float wr = gr[ml], wi = gi[ml];
                float fv_r, fv_i;
                if (odd) { fv_r = 0.5f * (zi + wi); fv_i = 0.5f * (wr - zr); }
                else     { fv_r = 0.5f * (zr + wr); fv_i = 0.5f * (zi - wi); }
                float re = fmaf(fv_r, SC_ORTHO, gfr[2048 + n] * SCC);
                float im = fmaf(fv_i, SC_ORTHO, gfi[2048 + n] * SCC);

                float s2 = re * re + im * im;
                float mag, sa, ca;
                if (s2 > 0.f) {
                    float inv = rsqrtf(s2);
                    mag = s2 * inv; sa = im * inv; ca = re * inv;
                } else { mag = 0.f; sa = 0.f; ca = 1.f; }
                float freqv = (float)n * 0.1953125f;

                float4 v;
                v.x = fmaxf(fmaf(mag, w0.x, fmaf(sa, w1.x, fmaf(ca, w2.x, fmaf(freqv, w3.x, bb.x)))), 0.f);
                v.y = fmaxf(fmaf(mag, w0.y, fmaf(sa, w1.y, fmaf(ca, w2.y, fmaf(freqv, w3.y, bb.y)))), 0.f);
                v.z = fmaxf(fmaf(mag, w0.z, fmaf(sa, w1.z, fmaf(ca, w2.z, fmaf(freqv, w3.z, bb.z)))), 0.f);
                v.w = fmaxf(fmaf(mag, w0.w, fmaf(sa, w1.w, fmaf(ca, w2.w, fmaf(freqv, w3.w, bb.w)))), 0.f);

                *(uint2*)(frow + (size_t)n * 64) =
                    make_uint2(packbf(v.x, v.y), packbf(v.z, v.w));

                float4 a = __ldg((const float4*)&mag_w[(size_t)n * 64 + h0]);
                float4 c = __ldg((const float4*)&ph_w[(size_t)n * 64 + h0]);
                float dm = 0.f, dp = 0.f;
                dm = fmaf(v.x, a.x, dm); dm = fmaf(v.y, a.y, dm);
                dm = fmaf(v.z, a.z, dm); dm = fmaf(v.w, a.w, dm);
                dp = fmaf(v.x, c.x, dp); dp = fmaf(v.y, c.y, dp);
                dp = fmaf(v.z, c.z, dp); dp = fmaf(v.w, c.w, dp);

#pragma unroll
                for (int off = 8; off >= 1; off >>= 1) {
                    dm += __shfl_xor_sync(0xffffffffu, dm, off, 16);
                    dp += __shfl_xor_sync(0xffffffffu, dp, off, 16);
                }
                if (lane16 == 0) {
                    size_t id = mrow + n;
                    g_fft_re[id] = re;
                    g_fft_im[id] = im;
                    float mo  = fmaxf(dm + __ldg(&mag_b[n]), 0.f);
                    float phv = 6.283185307179586f * sigf(dp + __ldg(&ph_b[n]));
                    float spv, cpv;
                    __sincosf(phv, &spv, &cpv);
                    g_new_re[id] = mo * cpv;
                    g_new_im[id] = mo * spv;
                }
            }
        }
    }
}

// ---------------- kernel 2: bf16 mma.sync split-K GEMM, 2-stage, 3 CTAs/SM ----------------
#define BK_       64
#define NCHUNK_   (K_/BK_)        // 257
#define ASTRIDE_W 36
#define A_WORDS_  (128*ASTRIDE_W)
#define B_WORDS_  (96*ASTRIDE_W)
#define STG_WORDS_ (A_WORDS_+B_WORDS_)
#define GEMM_SMEM_ (2*STG_WORDS_*4)     // 64512 bytes

__device__ __forceinline__ void load_chunk(uint32_t sbase, const __nv_bfloat16* __restrict__ Ab,
                                           const __nv_bfloat16* __restrict__ Bb, int kbase, int tid)
{
    uint32_t sA = sbase;
    uint32_t sB = sbase + A_WORDS_ * 4;
#pragma unroll
    for (int i = 0; i < 4; i++) {
        int g = tid + (i << 8);
        int r = g >> 3, c = g & 7;
        CP_ASYNC16(sA + (uint32_t)(r * (ASTRIDE_W*4) + c * 16),
                   Ab + (size_t)r * K_ + kbase + c * 8);
    }
#pragma unroll
    for (int i = 0; i < 3; i++) {
        int g = tid + (i << 8);
        int r = g >> 3, c = g & 7;
        CP_ASYNC16(sB + (uint32_t)(r * (ASTRIDE_W*4) + c * 16),
                   Bb + (size_t)r * K_ + kbase + c * 8);
    }
    asm volatile("cp.async.commit_group;\n" ::: "memory");
}

__global__ void __launch_bounds__(256, 3) k_gemm()
{
    extern __shared__ __align__(16) uint32_t smem[];

    int tid = threadIdx.x;
    int nt0 = blockIdx.x;
    int m0  = blockIdx.y * 128;
    int s   = blockIdx.z;
    const __nv_bfloat16* Ab = g_flat + (size_t)m0 * K_;
    const __nv_bfloat16* Bb = g_wt + (size_t)(nt0 * 96) * K_;

    int warp = tid >> 5, lane = tid & 31;
    int wm = warp & 3;
    int wn = warp >> 2;
    int lr = lane >> 2, lc = lane & 3;

    int li = lane >> 3, lrr = lane & 7;
    uint32_t aoff[2], boff[3];
#pragma unroll
    for (int mt = 0; mt < 2; mt++)
        aoff[mt] = (uint32_t)(((wm * 32 + mt * 16 + (li & 1) * 8 + lrr) * ASTRIDE_W + (li >> 1) * 4) * 4);
#pragma unroll
    for (int p = 0; p < 3; p++)
        boff[p] = (uint32_t)(((wn * 48 + (2 * p + (li >> 1)) * 8 + lrr) * ASTRIDE_W + (li & 1) * 4) * 4
                             + A_WORDS_ * 4);

    float acc[2][6][4];
#pragma unroll
    for (int i = 0; i < 2; i++)
#pragma unroll
        for (int j = 0; j < 6; j++)
#pragma unroll
            for (int q = 0; q < 4; q++) acc[i][j][q] = 0.f;

    const int cs = (s * NCHUNK_) / SPLITS_;
    const int ce = ((s + 1) * NCHUNK_) / SPLITS_;
    const int CN = ce - cs;

    uint32_t sb = smem_u32(smem);

    load_chunk(sb, Ab, Bb, cs * BK_, tid);

    for (int i = 0; i < CN; i++) {
        if (i + 1 < CN)
            load_chunk(sb + ((i + 1) & 1) * (STG_WORDS_ * 4), Ab, Bb, (cs + i + 1) * BK_, tid);
        else
            asm volatile("cp.async.commit_group;\n" ::: "memory");
        asm volatile("cp.async.wait_group 1;\n" ::: "memory");
        __syncthreads();

        uint32_t stage = sb + (uint32_t)((i & 1) * (STG_WORDS_ * 4));

#pragma unroll
        for (int kt = 0; kt < 4; kt++) {
            uint32_t kb = stage + (uint32_t)(kt * 32);
            uint32_t a[2][4];
            LDSM_X4(a[0][0], a[0][1], a[0][2], a[0][3], kb + aoff[0]);
            LDSM_X4(a[1][0], a[1][1], a[1][2], a[1][3], kb + aoff[1]);
            uint32_t bfr[6][2];
            LDSM_X4(bfr[0][0], bfr[0][1], bfr[1][0], bfr[1][1], kb + boff[0]);
            LDSM_X4(bfr[2][0], bfr[2][1], bfr[3][0], bfr[3][1], kb + boff[1]);
            LDSM_X4(bfr[4][0], bfr[4][1], bfr[5][0], bfr[5][1], kb + boff[2]);
#pragma unroll
            for (int mt = 0; mt < 2; mt++)
#pragma unroll
                for (int nt = 0; nt < 6; nt++)
                    mma_bf16(acc[mt][nt], a[mt], bfr[nt]);
        }
        __syncthreads();
    }

    float* P = g_part[s];
#pragma unroll
    for (int mt = 0; mt < 2; mt++) {
        int row = m0 + wm * 32 + mt * 16 + lr;
#pragma unroll
        for (int nt = 0; nt < 6; nt++) {
            int col = nt0 * 96 + wn * 48 + nt * 8 + lc * 2;
            float2 v0 = make_float2(acc[mt][nt][0], acc[mt][nt][1]);
            float2 v1 = make_float2(acc[mt][nt][2], acc[mt][nt][3]);
            *(float2*)(P + (size_t)row * NPAD_ + col)       = v0;
            *(float2*)(P + (size_t)(row + 8) * NPAD_ + col) = v1;
        }
    }
}

// ---------------- kernel 3: bwd — reduce+gate+blend + packed iFFTs + residual + LayerNorm ----------------
#define BWD_SMEMF 34048

__global__ void __launch_bounds__(512) k_bwd(
    const float* __restrict__ x, float* __restrict__ out,
    const float* __restrict__ bg,
    const float* __restrict__ gamma, const float* __restrict__ beta)
{
    extern __shared__ __align__(16) float sm[];
    int b = blockIdx.x, tid = threadIdx.x;

    float* r0  = sm;
    float* i0  = sm + 4096;
    float* r1  = sm + 8192;
    float* i1  = sm + 12288;
    float* fre = sm + 16384;   // [16][264]
    float* fim = sm + 20608;
    float* y   = sm + 24832;   // [512][17]
    float* tc  = sm + 33536;
    float* ts  = sm + 33792;

    if (tid < 256) {
        float _s, _c;
        sincosf(3.14159265358979323846f * (float)tid * (1.0f / 256.0f), &_s, &_c);
        tc[tid] = _c; ts[tid] = _s;
    }

    // split-K reduce + gate + blend
    for (int p = tid; p < 16 * NF_; p += 512) {
        int f = p / NF_;
        int n = p - f * NF_;
        int m = b * 16 + f;
        size_t pofs = (size_t)m * NPAD_ + n;
        float acc = 0.f;
#pragma unroll
        for (int s2 = 0; s2 < SPLITS_; s2++) acc += g_part[s2][pofs];
        float g = acc + __ldg(&bg[n]);
        g = g * sigf(g);
        float w = sigf(g);
        size_t id = (size_t)m * NF_ + n;
        fre[f * 264 + n] = w * g_new_re[id] + (1.f - w) * g_fft_re[id];
        fim[f * 264 + n] = w * g_new_im[id] + (1.f - w) * g_fft_im[id];
    }
    __syncthreads();

    // build 8 packed spectra: slot p holds Z = Fa + i*Fb, fa=2p, fb=2p+1 (hermitian extended)
#pragma unroll
    for (int i = 0; i < 8; i++) {
        int e = tid + i * 512;
        int p = e >> 9, pos = e & 511;
        int fa = (2 * p) * 264, fb = (2 * p + 1) * 264;
        float far, fai, fbr, fbi;
        if (pos == 0)        { far = fre[fa];       fai = 0.f;
                               fbr = fre[fb];       fbi = 0.f; }
        else if (pos < 256)  { far = fre[fa + pos]; fai = fim[fa + pos];
                               fbr = fre[fb + pos]; fbi = fim[fb + pos]; }
        else if (pos == 256) { far = fre[fa + 256]; fai = 0.f;
                               fbr = fre[fb + 256]; fbi = 0.f; }
        else                 { far = fre[fa + 512 - pos]; fai = -fim[fa + 512 - pos];
                               fbr = fre[fb + 512 - pos]; fbi = -fim[fb + 512 - pos]; }
        r0[p * 512 + pos] = far - fbi;
        i0[p * 512 + pos] = fai + fbr;
    }

    float *fr2, *fi2;
    fft512x8(r0, i0, r1, i1, tc, ts, tid, fr2, fi2);

#pragma unroll
    for (int i = 0; i < 8; i++) {
        int e = tid + i * 512;
        int p = e >> 9, t = e & 511;
        y[t * 17 + 2 * p]     = fr2[p * 512 + t] * SC_ORTHO;
        y[t * 17 + 2 * p + 1] = fi2[p * 512 + t] * SC_ORTHO;
    }
    __syncthreads();

    // residual + LayerNorm, thread t owns row t
    {
        int t = tid;
        const float4* xr = (const float4*)(x + ((size_t)(b * 512 + t)) * 16);
        float v[16];
#pragma unroll
        for (int q = 0; q < 4; q++) {
            float4 xv = xr[q];
            v[q * 4 + 0] = y[t * 17 + q * 4 + 0] + xv.x;
            v[q * 4 + 1] = y[t * 17 + q * 4 + 1] + xv.y;
            v[q * 4 + 2] = y[t * 17 + q * 4 + 2] + xv.z;
            v[q * 4 + 3] = y[t * 17 + q * 4 + 3] + xv.w;
        }
        float smv = 0.f;
#pragma unroll
        for (int i = 0; i < 16; i++) smv += v[i];
        float mu = smv * (1.f / 16.f);
        float ss = 0.f;
#pragma unroll
        for (int i = 0; i < 16; i++) { float d = v[i] - mu; ss = fmaf(d, d, ss); }
        float inv = rsqrtf(ss * (1.f / 16.f) + 1e-5f);
        float4* ov = (float4*)(out + ((size_t)(b * 512 + t)) * 16);
#pragma unroll
        for (int q = 0; q < 4; q++) {
            float4 o;
            o.x = (v[q * 4 + 0] - mu) * inv * __ldg(&gamma[q * 4 + 0]) + __ldg(&beta[q * 4 + 0]);
            o.y = (v[q * 4 + 1] - mu) * inv * __ldg(&gamma[q * 4 + 1]) + __ldg(&beta[q * 4 + 1]);
            o.z = (v[q * 4 + 2] - mu) * inv * __ldg(&gamma[q * 4 + 2]) + __ldg(&beta[q * 4 + 2]);
            o.w = (v[q * 4 + 3] - mu) * inv * __ldg(&gamma[q * 4 + 3]) + __ldg(&beta[q * 4 + 3]);
            ov[q] = o;
        }
    }
}

// ---------------- launcher: 3 kernels ----------------
extern "C" void kernel_launch(void* const* d_in, const int* in_sizes, int n_in,
                              void* d_out, int out_size)
{
    const float* x       = (const float*)d_in[0];
    const float* W_proj  = (const float*)d_in[1];
    const float* b_proj  = (const float*)d_in[2];
    const float* W_gate  = (const float*)d_in[3];
    const float* b_gate  = (const float*)d_in[4];
    const float* mag_w   = (const float*)d_in[5];
    const float* mag_b   = (const float*)d_in[6];
    const float* phase_w = (const float*)d_in[7];
    const float* phase_b = (const float*)d_in[8];
    const float* ln_g    = (const float*)d_in[9];
    const float* ln_b    = (const float*)d_in[10];
    float* out = (float*)d_out;

    cudaFuncSetAttribute(k_fwd,  cudaFuncAttributeMaxDynamicSharedMemorySize, FWD_SMEMF * 4);
    cudaFuncSetAttribute(k_gemm, cudaFuncAttributeMaxDynamicSharedMemorySize, GEMM_SMEM_);
    cudaFuncSetAttribute(k_bwd,  cudaFuncAttributeMaxDynamicSharedMemorySize, BWD_SMEMF * 4);

    k_fwd<<<NHEAVY_ + NT_BLKS_, 512, FWD_SMEMF * 4>>>(x, W_proj, b_proj, mag_w, mag_b,
                                                      phase_w, phase_b, W_gate);
    k_gemm<<<dim3(3, 16, SPLITS_), 256, GEMM_SMEM_>>>();
    k_bwd<<<B_, 512, BWD_SMEMF * 4>>>(x, out, b_gate, ln_g, ln_b);
}

// round 16
// speedup vs baseline: 1.6339x; 1.6339x over previous
#include <cuda_runtime.h>
#include <cuda_bf16.h>
#include <math.h>
#include <stdint.h>

#define B_    128
#define H_    512
#define F_    16
#define HID_  64
#define NF_   257
#define M_    (B_*F_)       // 2048
#define K_    (NF_*HID_)    // 16448
#define NPAD_ 288
#define SPLITS_ 9

// ---------------- scratch (static device memory; no allocations) ----------------
__device__ __align__(128) float g_fft_re[M_*NF_];
__device__ __align__(128) float g_fft_im[M_*NF_];
__device__ __align__(128) float g_new_re[M_*NF_];
__device__ __align__(128) float g_new_im[M_*NF_];
__device__ __align__(128) __nv_bfloat16 g_wt[(size_t)NPAD_*K_];   // W_gate^T [n][k] bf16
__device__ __align__(128) float g_part[SPLITS_][(size_t)M_*NPAD_];
__device__ __align__(128) __nv_bfloat16 g_flat[(size_t)M_*K_];    // proj bf16, [m][n*64+h]

// ================= helpers =================
#define CP_ASYNC16(dst, src) \
    asm volatile("cp.async.cg.shared.global [%0], [%1], 16;\n" :: "r"(dst), "l"(src))
__device__ __forceinline__ uint32_t smem_u32(const void* p) {
    uint32_t a;
    asm("{ .reg .u64 t; cvta.to.shared.u64 t, %1; cvt.u32.u64 %0, t; }" : "=r"(a) : "l"(p));
    return a;
}
__device__ __forceinline__ void mma_bf16(float c[4], const uint32_t a[4], const uint32_t b[2]) {
    asm volatile(
        "mma.sync.aligned.m16n8k16.row.col.f32.bf16.bf16.f32 "
        "{%0,%1,%2,%3}, {%4,%5,%6,%7}, {%8,%9}, {%0,%1,%2,%3};"
        : "+f"(c[0]), "+f"(c[1]), "+f"(c[2]), "+f"(c[3])
        : "r"(a[0]), "r"(a[1]), "r"(a[2]), "r"(a[3]), "r"(b[0]), "r"(b[1]));
}
#define LDSM_X4(R0, R1, R2, R3, ADDR) \
    asm volatile("ldmatrix.sync.aligned.m8n8.x4.shared.b16 {%0,%1,%2,%3}, [%4];" \
        : "=r"(R0), "=r"(R1), "=r"(R2), "=r"(R3) : "r"(ADDR))
__device__ __forceinline__ uint32_t packbf(float x, float y) {
    __nv_bfloat162 h = __float22bfloat162_rn(make_float2(x, y));
    return *(uint32_t*)&h;
}
__device__ __forceinline__ float sigf(float x) {
    return __fdividef(1.f, 1.f + __expf(-x));
}
#define SC_ORTHO 0.044194173824159216f

// ---------------- batched N-channel 512-pt Stockham FFT (512 threads, 4 ch/thread) ----------------
__device__ __forceinline__ void fft512x8(float* r0, float* i0, float* r1, float* i1,
                                         const float* tc, const float* ts,
                                         int tid, float*& outr, float*& outi)
{
    float *ar = r0, *ai = i0, *br = r1, *bi = i1;
    int u = tid & 255, cb = (tid >> 8) << 2;
#pragma unroll
    for (int st = 0; st < 9; st++) {
        __syncthreads();
        int m = 1 << st;
        int j = u >> st, k = u & (m - 1), idx = u & ~(m - 1);
        float wc = tc[idx], ws = ts[idx];
        int o0 = k + (j << (st + 1));
#pragma unroll
        for (int q = 0; q < 4; q++) {
            int off = (cb + q) << 9;
            float c0r = ar[off + u],       c0i = ai[off + u];
            float c1r = ar[off + u + 256], c1i = ai[off + u + 256];
            float sr = c0r - c1r, si = c0i - c1i;
            br[off + o0]     = c0r + c1r;
            bi[off + o0]     = c0i + c1i;
            br[off + o0 + m] = wc * sr - ws * si;
            bi[off + o0 + m] = wc * si + ws * sr;
        }
        float* t;
        t = ar; ar = br; br = t;
        t = ai; ai = bi; bi = t;
    }
    __syncthreads();
    outr = ar; outi = ai;
}

// 8-channel FFT with 1024 threads (2 ch/thread)
__device__ __forceinline__ void fft512x8w(float* r0, float* i0, float* r1, float* i1,
                                          const float* tc, const float* ts,
                                          int tid, float*& outr, float*& outi)
{
    float *ar = r0, *ai = i0, *br = r1, *bi = i1;
    int u = tid & 255, cb = (tid >> 8) << 1;   // tid>>8 in 0..3 -> cb {0,2,4,6}
#pragma unroll
    for (int st = 0; st < 9; st++) {
        __syncthreads();
        int m = 1 << st;
        int j = u >> st, k = u & (m - 1), idx = u & ~(m - 1);
        float wc = tc[idx], ws = ts[idx];
        int o0 = k + (j << (st + 1));
#pragma unroll
        for (int q = 0; q < 2; q++) {
            int off = (cb + q) << 9;
            float c0r = ar[off + u],       c0i = ai[off + u];
            float c1r = ar[off + u + 256], c1i = ai[off + u + 256];
            float sr = c0r - c1r, si = c0i - c1i;
            br[off + o0]     = c0r + c1r;
            bi[off + o0]     = c0i + c1i;
            br[off + o0 + m] = wc * sr - ws * si;
            bi[off + o0 + m] = wc * si + ws * sr;
        }
        float* t;
        t = ar; ar = br; br = t;
        t = ai; ai = bi; bi = t;
    }
    __syncthreads();
    outr = ar; outi = ai;
}

// 5-channel: channels {tid>>8, 2+(tid>>8)} for all threads, channel 4 for tid<256
__device__ __forceinline__ void fft512x5(float* r0, float* i0, float* r1, float* i1,
                                         const float* tc, const float* ts,
                                         int tid, float*& outr, float*& outi)
{
    float *ar = r0, *ai = i0, *br = r1, *bi = i1;
    int u = tid & 255;
    int c0ch = tid >> 8;            // 0 or 1
#pragma unroll
    for (int st = 0; st < 9; st++) {
        __syncthreads();
        int m = 1 << st;
        int j = u >> st, k = u & (m - 1), idx = u & ~(m - 1);
        float wc = tc[idx], ws = ts[idx];
        int o0 = k + (j << (st + 1));
#pragma unroll
        for (int q = 0; q < 2; q++) {
            int off = (c0ch + q * 2) << 9;
            float c0r = ar[off + u],       c0i = ai[off + u];
            float c1r = ar[off + u + 256], c1i = ai[off + u + 256];
            float sr = c0r - c1r, si = c0i - c1i;
            br[off + o0]     = c0r + c1r;
            bi[off + o0]     = c0i + c1i;
            br[off + o0 + m] = wc * sr - ws * si;
            bi[off + o0 + m] = wc * si + ws * sr;
        }
        if (tid < 256) {
            int off = 4 << 9;
            float c0r = ar[off + u],       c0i = ai[off + u];
            float c1r = ar[off + u + 256], c1i = ai[off + u + 256];
            float sr = c0r - c1r, si = c0i - c1i;
            br[off + o0]     = c0r + c1r;
            bi[off + o0]     = c0i + c1i;
            br[off + o0 + m] = wc * sr - ws * si;
            bi[off + o0 + m] = wc * si + ws * sr;
        }
        float* t;
        t = ar; ar = br; br = t;
        t = ai; ai = bi; bi = t;
    }
    __syncthreads();
    outr = ar; outi = ai;
}

// ---------------- kernel 1: fwd — R14 version (packed real FFTs, inline unpack) ----------------
// smem floats: r0 @0 (2560), i0 @2560, r1 @5120, i1 @7680, s @10240 (512),
// sp @10752 (1024), tc @11776 (256), ts @12032 (256), wp @12288 (256), bp @12544 (64)
#define FWD_SMEMF 12608
#define NHEAVY_   (B_*2)    // 256 (batch, channel-half) blocks
#define NT_BLKS_  (257*9)   // 2313 transpose tiles (64k x 32n)

__global__ void __launch_bounds__(512) k_fwd(
    const float* __restrict__ x,
    const float* __restrict__ Wp,  const float* __restrict__ bp,
    const float* __restrict__ mag_w, const float* __restrict__ mag_b,
    const float* __restrict__ ph_w,  const float* __restrict__ ph_b,
    const float* __restrict__ Wg)
{
    extern __shared__ __align__(16) float sm[];
    int tid = threadIdx.x;

    if (blockIdx.x >= NHEAVY_) {
        // ---- transpose tile: Wg[K][257] -> g_wt[288][K] bf16 (zero pad) ----
        float* tile = sm;                       // [64][33]
        int t  = blockIdx.x - NHEAVY_;
        int kt = t % 257, nt = t / 257;
        int kb = kt * 64, nb = nt * 32;
        int col = tid & 31, rowb = tid >> 5;
#pragma unroll
        for (int rr = 0; rr < 4; rr++) {
            int row = rowb + rr * 16;
            int nn = nb + col;
            tile[row * 33 + col] = (nn < NF_) ? Wg[(size_t)(kb + row) * NF_ + nn] : 0.f;
        }
        __syncthreads();
#pragma unroll
        for (int i = 0; i < 4; i++) {
            int e = tid + i * 512;
            int nl = e >> 6, kl = e & 63;
            g_wt[(size_t)(nb + nl) * K_ + kb + kl] = __float2bfloat16(tile[kl * 33 + nl]);
        }
        return;
    }

    // ---- heavy block: batch b, channel-half g ----
    int b = blockIdx.x >> 1;
    int g = blockIdx.x & 1;
    float* r0  = sm;
    float* i0  = sm + 2560;
    float* r1  = sm + 5120;
    float* i1  = sm + 7680;
    float* s   = sm + 10240;
    float* sp  = sm + 10752;   // zero-padded: sp[i] = s[i-255] for i in [255,767)
    float* tc  = sm + 11776;
    float* ts  = sm + 12032;
    float* wp  = sm + 12288;
    float* bpp = sm + 12544;

    if (tid < 256) {
        float _s, _c;
        sincosf(-3.14159265358979323846f * (float)tid * (1.0f / 256.0f), &_s, &_c);
        tc[tid] = _c; ts[tid] = _s;
    } else {
        wp[tid - 256] = Wp[tid - 256];
    }
    if (tid < 64) bpp[tid] = bp[tid];

    // channel sum -> s, zero sp wings; also load 8 packed channels (4 complex)
    {
        const float4* xr = (const float4*)(x + (size_t)b * 512 * 16);
        float4 a = xr[tid * 4 + 0], c = xr[tid * 4 + 1], d = xr[tid * 4 + 2], e = xr[tid * 4 + 3];
        s[tid] = (a.x + a.y + a.z + a.w) + (c.x + c.y + c.z + c.w)
               + (d.x + d.y + d.z + d.w) + (e.x + e.y + e.z + e.w);
        sp[tid] = 0.f;
        sp[512 + tid] = 0.f;
#pragma unroll
        for (int i = 0; i < 2; i++) {
            int e2 = tid + i * 512;           // 0..1023
            int t = e2 >> 1, j = e2 & 1;
            float4 v = xr[t * 4 + g * 2 + j];
            int p0 = j * 2;
            r0[(p0 + 0) * 512 + t] = v.x; i0[(p0 + 0) * 512 + t] = v.y;
            r0[(p0 + 1) * 512 + t] = v.z; i0[(p0 + 1) * 512 + t] = v.w;
        }
    }
    __syncthreads();
    sp[255 + tid] = s[tid];
    __syncthreads();

    // autocorrelation -> slot 4 (csd channel)
    {
        int t = tid;
        float acc0 = 0.f, acc1 = 0.f, acc2 = 0.f, acc3 = 0.f;
#pragma unroll 4
        for (int k = 0; k < 512; k += 4) {
            float4 sk = *(const float4*)&s[k];
            acc0 = fmaf(sp[t + k + 0], sk.x, acc0);
            acc1 = fmaf(sp[t + k + 1], sk.y, acc1);
            acc2 = fmaf(sp[t + k + 2], sk.z, acc2);
            acc3 = fmaf(sp[t + k + 3], sk.w, acc3);
        }
        r0[2048 + t] = (acc0 + acc1) + (acc2 + acc3);
        i0[2048 + t] = 0.f;
    }

    float *gfr, *gfi;
    fft512x5(r0, i0, r1, i1, tc, ts, tid, gfr, gfi);

    // features + proj + heads: 16-lane team per (ch, n), two-for-one unpack inline
    {
        const float SCC = SC_ORTHO / 256.0f;
        int lane16 = tid & 15;         // h-chunk owner: h in [lane16*4, lane16*4+4)
        int team   = tid >> 4;         // 32 teams
        int h0 = lane16 * 4;
        float4 w0 = *(const float4*)&wp[h0];
        float4 w1 = *(const float4*)&wp[64 + h0];
        float4 w2 = *(const float4*)&wp[128 + h0];
        float4 w3 = *(const float4*)&wp[192 + h0];
        float4 bb = *(const float4*)&bpp[h0];

        const int NITEM = 8 * NF_;     // 2056
        for (int it = team; it < NITEM; it += 32) {
            int ch = it / NF_;
            int n  = it - ch * NF_;
            int m  = b * 16 + g * 8 + ch;
            size_t id = (size_t)m * NF_ + n;

            int p  = ch >> 1, odd = ch & 1;
            int ml = (512 - n) & 511;
            float zr = gfr[p * 512 + n],  zi = gfi[p * 512 + n];
            float wr = gfr[p * 512 + ml], wi = gfi[p * 512 + ml];
            float fav_r = 0.5f * (zr + wr), fav_i = 0.5f * (zi - wi);
            float fbv_r = 0.5f * (zi + wi), fbv_i = 0.5f * (wr - zr);
            float fv_r = odd ? fbv_r : fav_r;
            float fv_i = odd ? fbv_i : fav_i;
            float re = fv_r * SC_ORTHO + gfr[2048 + n] * SCC;
            float im = fv_i * SC_ORTHO + gfi[2048 + n] * SCC;

            float s2 = re * re + im * im;
            float mag, sa, ca;
            if (s2 > 0.f) {
                float inv = rsqrtf(s2);
                mag = s2 * inv; sa = im * inv; ca = re * inv;
            } else { mag = 0.f; sa = 0.f; ca = 1.f; }
            float freqv = (float)n * 0.1953125f;

            float4 v;
            v.x = fmaxf(fmaf(mag, w0.x, fmaf(sa, w1.x, fmaf(ca, w2.x, fmaf(freqv, w3.x, bb.x)))), 0.f);
            v.y = fmaxf(fmaf(mag, w0.y, fmaf(sa, w1.y, fmaf(ca, w2.y, fmaf(freqv, w3.y, bb.y)))), 0.f);
            v.z = fmaxf(fmaf(mag, w0.z, fmaf(sa, w1.z, fmaf(ca, w2.z, fmaf(freqv, w3.z, bb.z)))), 0.f);
            v.w = fmaxf(fmaf(mag, w0.w, fmaf(sa, w1.w, fmaf(ca, w2.w, fmaf(freqv, w3.w, bb.w)))), 0.f);

            *(uint2*)(g_flat + (size_t)m * K_ + (size_t)n * 64 + h0) =
                make_uint2(packbf(v.x, v.y), packbf(v.z, v.w));

            float4 a = __ldg((const float4*)&mag_w[(size_t)n * 64 + h0]);
            float4 c = __ldg((const float4*)&ph_w[(size_t)n * 64 + h0]);
            float dm = 0.f, dp = 0.f;
            dm = fmaf(v.x, a.x, dm); dm = fmaf(v.y, a.y, dm);
            dm = fmaf(v.z, a.z, dm); dm = fmaf(v.w, a.w, dm);
            dp = fmaf(v.x, c.x, dp); dp = fmaf(v.y, c.y, dp);
            dp = fmaf(v.z, c.z, dp); dp = fmaf(v.w, c.w, dp);

#pragma unroll
            for (int off = 8; off >= 1; off >>= 1) {
                dm += __shfl_xor_sync(0xffffffffu, dm, off, 16);
                dp += __shfl_xor_sync(0xffffffffu, dp, off, 16);
            }
            if (lane16 == 0) {
                g_fft_re[id] = re;
                g_fft_im[id] = im;
                float mo  = fmaxf(dm + __ldg(&mag_b[n]), 0.f);
                float phv = 6.283185307179586f * sigf(dp + __ldg(&ph_b[n]));
                float spv, cpv;
                __sincosf(phv, &spv, &cpv);
                g_new_re[id] = mo * cpv;
                g_new_im[id] = mo * spv;
            }
        }
    }
}

// ---------------- kernel 2: bf16 mma.sync split-K GEMM, 2-stage, 3 CTAs/SM ----------------
#define BK_       64
#define NCHUNK_   (K_/BK_)        // 257
#define ASTRIDE_W 36
#define A_WORDS_  (128*ASTRIDE_W)
#define B_WORDS_  (96*ASTRIDE_W)
#define STG_WORDS_ (A_WORDS_+B_WORDS_)
#define GEMM_SMEM_ (2*STG_WORDS_*4)     // 64512 bytes

__device__ __forceinline__ void load_chunk(uint32_t sbase, const __nv_bfloat16* __restrict__ Ab,
                                           const __nv_bfloat16* __restrict__ Bb, int kbase, int tid)
{
    uint32_t sA = sbase;
    uint32_t sB = sbase + A_WORDS_ * 4;
#pragma unroll
    for (int i = 0; i < 4; i++) {
        int g = tid + (i << 8);
        int r = g >> 3, c = g & 7;
        CP_ASYNC16(sA + (uint32_t)(r * (ASTRIDE_W*4) + c * 16),
                   Ab + (size_t)r * K_ + kbase + c * 8);
    }
#pragma unroll
    for (int i = 0; i < 3; i++) {
        int g = tid + (i << 8);
        int r = g >> 3, c = g & 7;
        CP_ASYNC16(sB + (uint32_t)(r * (ASTRIDE_W*4) + c * 16),
                   Bb + (size_t)r * K_ + kbase + c * 8);
    }
    asm volatile("cp.async.commit_group;\n" ::: "memory");
}

__global__ void __launch_bounds__(256, 3) k_gemm()
{
    extern __shared__ __align__(16) uint32_t smem[];

    int tid = threadIdx.x;
    int nt0 = blockIdx.x;
    int m0  = blockIdx.y * 128;
    int s   = blockIdx.z;
    const __nv_bfloat16* Ab = g_flat + (size_t)m0 * K_;
    const __nv_bfloat16* Bb = g_wt + (size_t)(nt0 * 96) * K_;

    int warp = tid >> 5, lane = tid & 31;
    int wm = warp & 3;
    int wn = warp >> 2;
    int lr = lane >> 2, lc = lane & 3;

    int li = lane >> 3, lrr = lane & 7;
    uint32_t aoff[2], boff[3];
#pragma unroll
    for (int mt = 0; mt < 2; mt++)
        aoff[mt] = (uint32_t)(((wm * 32 + mt * 16 + (li & 1) * 8 + lrr) * ASTRIDE_W + (li >> 1) * 4) * 4);
#pragma unroll
    for (int p = 0; p < 3; p++)
        boff[p] = (uint32_t)(((wn * 48 + (2 * p + (li >> 1)) * 8 + lrr) * ASTRIDE_W + (li & 1) * 4) * 4
                             + A_WORDS_ * 4);

    float acc[2][6][4];
#pragma unroll
    for (int i = 0; i < 2; i++)
#pragma unroll
        for (int j = 0; j < 6; j++)
#pragma unroll
            for (int q = 0; q < 4; q++) acc[i][j][q] = 0.f;

    const int cs = (s * NCHUNK_) / SPLITS_;
    const int ce = ((s + 1) * NCHUNK_) / SPLITS_;
    const int CN = ce - cs;

    uint32_t sb = smem_u32(smem);

    load_chunk(sb, Ab, Bb, cs * BK_, tid);

    for (int i = 0; i < CN; i++) {
        if (i + 1 < CN)
            load_chunk(sb + ((i + 1) & 1) * (STG_WORDS_ * 4), Ab, Bb, (cs + i + 1) * BK_, tid);
        else
            asm volatile("cp.async.commit_group;\n" ::: "memory");
        asm volatile("cp.async.wait_group 1;\n" ::: "memory");
        __syncthreads();

        uint32_t stage = sb + (uint32_t)((i & 1) * (STG_WORDS_ * 4));

#pragma unroll
        for (int kt = 0; kt < 4; kt++) {
            uint32_t kb = stage + (uint32_t)(kt * 32);
            uint32_t a[2][4];
            LDSM_X4(a[0][0], a[0][1], a[0][2], a[0][3], kb + aoff[0]);
            LDSM_X4(a[1][0], a[1][1], a[1][2], a[1][3], kb + aoff[1]);
            uint32_t bfr[6][2];
            LDSM_X4(bfr[0][0], bfr[0][1], bfr[1][0], bfr[1][1], kb + boff[0]);
            LDSM_X4(bfr[2][0], bfr[2][1], bfr[3][0], bfr[3][1], kb + boff[1]);
            LDSM_X4(bfr[4][0], bfr[4][1], bfr[5][0], bfr[5][1], kb + boff[2]);
#pragma unroll
            for (int mt = 0; mt < 2; mt++)
#pragma unroll
                for (int nt = 0; nt < 6; nt++)
                    mma_bf16(acc[mt][nt], a[mt], bfr[nt]);
        }
        __syncthreads();
    }

    float* P = g_part[s];
#pragma unroll
    for (int mt = 0; mt < 2; mt++) {
        int row = m0 + wm * 32 + mt * 16 + lr;
#pragma unroll
        for (int nt = 0; nt < 6; nt++) {
            int col = nt0 * 96 + wn * 48 + nt * 8 + lc * 2;
            float2 v0 = make_float2(acc[mt][nt][0], acc[mt][nt][1]);
            float2 v1 = make_float2(acc[mt][nt][2], acc[mt][nt][3]);
            *(float2*)(P + (size_t)row * NPAD_ + col)       = v0;
            *(float2*)(P + (size_t)(row + 8) * NPAD_ + col) = v1;
        }
    }
}

// ---------------- kernel 3: bwd — 1024 threads: reduce+gate+blend + packed iFFTs + LN ----------------
#define BWD_SMEMF 34048

__global__ void __launch_bounds__(1024) k_bwd(
    const float* __restrict__ x, float* __restrict__ out,
    const float* __restrict__ bg,
    const float* __restrict__ gamma, const float* __restrict__ beta)
{
    extern __shared__ __align__(16) float sm[];
    int b = blockIdx.x, tid = threadIdx.x;

    float* r0  = sm;
    float* i0  = sm + 4096;
    float* r1  = sm + 8192;
    float* i1  = sm + 12288;
    float* fre = sm + 16384;   // [16][264]
    float* fim = sm + 20608;
    float* y   = sm + 24832;   // [512][17]
    float* tc  = sm + 33536;
    float* ts  = sm + 33792;

    if (tid < 256) {
        float _s, _c;
        sincosf(3.14159265358979323846f * (float)tid * (1.0f / 256.0f), &_s, &_c);
        tc[tid] = _c; ts[tid] = _s;
    }

    // split-K reduce + gate + blend
    for (int p = tid; p < 16 * NF_; p += 1024) {
        int f = p / NF_;
        int n = p - f * NF_;
        int m = b * 16 + f;
        size_t pofs = (size_t)m * NPAD_ + n;
        float acc = 0.f;
#pragma unroll
        for (int s2 = 0; s2 < SPLITS_; s2++) acc += g_part[s2][pofs];
        float g = acc + __ldg(&bg[n]);
        g = g * sigf(g);
        float w = sigf(g);
        size_t id = (size_t)m * NF_ + n;
        fre[f * 264 + n] = w * g_new_re[id] + (1.f - w) * g_fft_re[id];
        fim[f * 264 + n] = w * g_new_im[id] + (1.f - w) * g_fft_im[id];
    }
    __syncthreads();

    // build 8 packed spectra: slot p holds Z = Fa + i*Fb, fa=2p, fb=2p+1 (hermitian extended)
#pragma unroll
    for (int i = 0; i < 4; i++) {
        int e = tid + i * 1024;
        int p = e >> 9, pos = e & 511;
        int fa = (2 * p) * 264, fb = (2 * p + 1) * 264;
        float far, fai, fbr, fbi;
        if (pos == 0)        { far = fre[fa];       fai = 0.f;
                               fbr = fre[fb];       fbi = 0.f; }
        else if (pos < 256)  { far = fre[fa + pos]; fai = fim[fa + pos];
                               fbr = fre[fb + pos]; fbi = fim[fb + pos]; }
        else if (pos == 256) { far = fre[fa + 256]; fai = 0.f;
                               fbr = fre[fb + 256]; fbi = 0.f; }
        else                 { far = fre[fa + 512 - pos]; fai = -fim[fa + 512 - pos];
                               fbr = fre[fb + 512 - pos]; fbi = -fim[fb + 512 - pos]; }
        r0[p * 512 + pos] = far - fbi;
        i0[p * 512 + pos] = fai + fbr;
    }

    float *fr2, *fi2;
    fft512x8w(r0, i0, r1, i1, tc, ts, tid, fr2, fi2);

#pragma unroll
    for (int i = 0; i < 4; i++) {
        int e = tid + i * 1024;
        int p = e >> 9, t = e & 511;
        y[t * 17 + 2 * p]     = fr2[p * 512 + t] * SC_ORTHO;
        y[t * 17 + 2 * p + 1] = fi2[p * 512 + t] * SC_ORTHO;
    }
    __syncthreads();

    // residual + LayerNorm, threads <512 own row t
    if (tid < 512) {
        int t = tid;
        const float4* xr = (const float4*)(x + ((size_t)(b * 512 + t)) * 16);
        float v[16];
#pragma unroll
        for (int q = 0; q < 4; q++) {
            float4 xv = xr[q];
            v[q * 4 + 0] = y[t * 17 + q * 4 + 0] + xv.x;
            v[q * 4 + 1] = y[t * 17 + q * 4 + 1] + xv.y;
            v[q * 4 + 2] = y[t * 17 + q * 4 + 2] + xv.z;
            v[q * 4 + 3] = y[t * 17 + q * 4 + 3] + xv.w;
        }
        float smv = 0.f;
#pragma unroll
        for (int i = 0; i < 16; i++) smv += v[i];
        float mu = smv * (1.f / 16.f);
        float ss = 0.f;
#pragma unroll
        for (int i = 0; i < 16; i++) { float d = v[i] - mu; ss = fmaf(d, d, ss); }
        float inv = rsqrtf(ss * (1.f / 16.f) + 1e-5f);
        float4* ov = (float4*)(out + ((size_t)(b * 512 + t)) * 16);
#pragma unroll
        for (int q = 0; q < 4; q++) {
            float4 o;
            o.x = (v[q * 4 + 0] - mu) * inv * __ldg(&gamma[q * 4 + 0]) + __ldg(&beta[q * 4 + 0]);
            o.y = (v[q * 4 + 1] - mu) * inv * __ldg(&gamma[q * 4 + 1]) + __ldg(&beta[q * 4 + 1]);
            o.z = (v[q * 4 + 2] - mu) * inv * __ldg(&gamma[q * 4 + 2]) + __ldg(&beta[q * 4 + 2]);
            o.w = (v[q * 4 + 3] - mu) * inv * __ldg(&gamma[q * 4 + 3]) + __ldg(&beta[q * 4 + 3]);
            ov[q] = o;
        }
    }
}

// ---------------- launcher: 3 kernels ----------------
extern "C" void kernel_launch(void* const* d_in, const int* in_sizes, int n_in,
                              void* d_out, int out_size)
{
    const float* x       = (const float*)d_in[0];
    const float* W_proj  = (const float*)d_in[1];
    const float* b_proj  = (const float*)d_in[2];
    const float* W_gate  = (const float*)d_in[3];
    const float* b_gate  = (const float*)d_in[4];
    const float* mag_w   = (const float*)d_in[5];
    const float* mag_b   = (const float*)d_in[6];
    const float* phase_w = (const float*)d_in[7];
    const float* phase_b = (const float*)d_in[8];
    const float* ln_g    = (const float*)d_in[9];
    const float* ln_b    = (const float*)d_in[10];
    float* out = (float*)d_out;

    cudaFuncSetAttribute(k_fwd,  cudaFuncAttributeMaxDynamicSharedMemorySize, FWD_SMEMF * 4);
    cudaFuncSetAttribute(k_gemm, cudaFuncAttributeMaxDynamicSharedMemorySize, GEMM_SMEM_);
    cudaFuncSetAttribute(k_bwd,  cudaFuncAttributeMaxDynamicSharedMemorySize, BWD_SMEMF * 4);

    k_fwd<<<NHEAVY_ + NT_BLKS_, 512, FWD_SMEMF * 4>>>(x, W_proj, b_proj, mag_w, mag_b,
                                                      phase_w, phase_b, W_gate);
    k_gemm<<<dim3(3, 16, SPLITS_), 256, GEMM_SMEM_>>>();
    k_bwd<<<B_, 1024, BWD_SMEMF * 4>>>(x, out, b_gate, ln_g, ln_b);
}